// round 2
// baseline (speedup 1.0000x reference)
#include <cuda_runtime.h>
#include <math.h>

#define T_TOKENS 65536
#define D_MODEL  256
#define E_EXPERTS 8
#define F_FF     1024
#define CAP      10240   // ceil(1.25 * 65536 / 8)

// ---------------- scratch (device globals; no allocation allowed) ----------
__device__ float g_buf[(size_t)E_EXPERTS * CAP * D_MODEL];   // 80 MB dispatch buffer
__device__ float g_hmid[(size_t)E_EXPERTS * CAP * F_FF];     // 320 MB mid activations
__device__ int   g_idx[T_TOKENS];
__device__ float g_prb[T_TOKENS];
__device__ int   g_slot_token[E_EXPERTS * CAP];
__device__ float g_slot_prob[E_EXPERTS * CAP];
__device__ int   g_count[E_EXPERTS];

// ---------------- zero-fill output (dropped tokens stay 0) -----------------
__global__ void zero_kernel(float4* __restrict__ out, int n4) {
    int i = blockIdx.x * blockDim.x + threadIdx.x;
    if (i < n4) out[i] = make_float4(0.f, 0.f, 0.f, 0.f);
}

// ---------------- gate: logits -> softmax prob of argmax + expert idx ------
__global__ void gate_kernel(const float* __restrict__ x,
                            const float* __restrict__ gw,
                            const float* __restrict__ gb) {
    __shared__ float s_gw[D_MODEL * E_EXPERTS];
    int tid = threadIdx.x;
    for (int i = tid; i < D_MODEL * E_EXPERTS; i += 256) s_gw[i] = gw[i];
    __syncthreads();

    int warp = tid >> 5, lane = tid & 31;
    int t = blockIdx.x * 8 + warp;
    const float* xr = x + (size_t)t * D_MODEL;

    float acc[E_EXPERTS];
#pragma unroll
    for (int e = 0; e < E_EXPERTS; e++) acc[e] = 0.f;

#pragma unroll
    for (int j = 0; j < 8; j++) {
        int d = j * 32 + lane;
        float xv = xr[d];
#pragma unroll
        for (int e = 0; e < E_EXPERTS; e++) acc[e] += xv * s_gw[d * E_EXPERTS + e];
    }
#pragma unroll
    for (int o = 16; o > 0; o >>= 1) {
#pragma unroll
        for (int e = 0; e < E_EXPERTS; e++)
            acc[e] += __shfl_xor_sync(0xffffffffu, acc[e], o);
    }
    if (lane == 0) {
        float lg[E_EXPERTS];
        float m = -INFINITY;
        int am = 0;
#pragma unroll
        for (int e = 0; e < E_EXPERTS; e++) {
            lg[e] = acc[e] + gb[e];
            if (lg[e] > m) { m = lg[e]; am = e; }   // strict > keeps first max
        }
        float s = 0.f;
#pragma unroll
        for (int e = 0; e < E_EXPERTS; e++) s += expf(lg[e] - m);
        g_idx[t] = am;
        g_prb[t] = 1.0f / s;   // exp(l_max - m) == 1
    }
}

// ---------------- ordered per-expert rank (token-order prefix scan) --------
__global__ void scan_kernel() {
    __shared__ int s[1024][E_EXPERTS];
    int tid = threadIdx.x;
    int base = tid * (T_TOKENS / 1024);   // 64 tokens per thread

    int cnt[E_EXPERTS];
#pragma unroll
    for (int e = 0; e < E_EXPERTS; e++) cnt[e] = 0;
    for (int i = 0; i < T_TOKENS / 1024; i++) cnt[g_idx[base + i]]++;

#pragma unroll
    for (int e = 0; e < E_EXPERTS; e++) s[tid][e] = cnt[e];
    __syncthreads();

    for (int off = 1; off < 1024; off <<= 1) {
        int v[E_EXPERTS];
        if (tid >= off) {
#pragma unroll
            for (int e = 0; e < E_EXPERTS; e++) v[e] = s[tid - off][e];
        }
        __syncthreads();
        if (tid >= off) {
#pragma unroll
            for (int e = 0; e < E_EXPERTS; e++) s[tid][e] += v[e];
        }
        __syncthreads();
    }

    int run[E_EXPERTS];
#pragma unroll
    for (int e = 0; e < E_EXPERTS; e++) run[e] = s[tid][e] - cnt[e];  // exclusive
    if (tid == 1023) {
#pragma unroll
        for (int e = 0; e < E_EXPERTS; e++) g_count[e] = min(s[1023][e], CAP);
    }

    for (int i = 0; i < T_TOKENS / 1024; i++) {
        int t = base + i;
        int e = g_idx[t];
        int pos = run[e]++;
        if (pos < CAP) {
            int slot = e * CAP + pos;
            g_slot_token[slot] = t;
            g_slot_prob[slot]  = g_prb[t];
        }
    }
}

// ---------------- dispatch: copy kept token rows into expert buffers -------
__global__ void dispatch_kernel(const float* __restrict__ x) {
    int slot = blockIdx.x * 4 + (threadIdx.x >> 6);
    int e = slot / CAP, c = slot % CAP;
    if (c >= g_count[e]) return;
    int t = g_slot_token[slot];
    int i = threadIdx.x & 63;
    const float4* src = (const float4*)(x + (size_t)t * D_MODEL);
    float4* dst = (float4*)(g_buf + (size_t)slot * D_MODEL);
    dst[i] = src[i];
}

// ---------------- GEMM1: hmid = relu(buf @ w1 + b1) ------------------------
// A: [CAP,256] per expert   B: [256,1024] per expert   tile 128x128, BK=8
__global__ __launch_bounds__(256) void gemm1_kernel(const float* __restrict__ w1,
                                                    const float* __restrict__ b1) {
    int e  = blockIdx.z;
    int m0 = blockIdx.y * 128;
    int n0 = blockIdx.x * 128;
    if (m0 >= g_count[e]) return;

    const float* A = g_buf + (size_t)e * CAP * D_MODEL;
    const float* B = w1    + (size_t)e * D_MODEL * F_FF;

    __shared__ float As[8][128];
    __shared__ float Bs[8][128];

    int tid = threadIdx.x;
    int tx = tid & 15, ty = tid >> 4;
    int a_row = tid >> 1,  a_k = (tid & 1) * 4;
    int b_row = tid >> 5,  b_c = (tid & 31) * 4;

    float acc[8][8];
#pragma unroll
    for (int i = 0; i < 8; i++)
#pragma unroll
        for (int j = 0; j < 8; j++) acc[i][j] = 0.f;

    for (int k0 = 0; k0 < D_MODEL; k0 += 8) {
        float4 av = *(const float4*)(A + (size_t)(m0 + a_row) * D_MODEL + k0 + a_k);
        As[a_k + 0][a_row] = av.x; As[a_k + 1][a_row] = av.y;
        As[a_k + 2][a_row] = av.z; As[a_k + 3][a_row] = av.w;
        *(float4*)(&Bs[b_row][b_c]) =
            *(const float4*)(B + (size_t)(k0 + b_row) * F_FF + n0 + b_c);
        __syncthreads();
#pragma unroll
        for (int kk = 0; kk < 8; kk++) {
            float a[8], b[8];
#pragma unroll
            for (int i = 0; i < 8; i++) a[i] = As[kk][ty + i * 16];
#pragma unroll
            for (int j = 0; j < 8; j++) b[j] = Bs[kk][tx + j * 16];
#pragma unroll
            for (int i = 0; i < 8; i++)
#pragma unroll
                for (int j = 0; j < 8; j++) acc[i][j] += a[i] * b[j];
        }
        __syncthreads();
    }

    float* Hm = g_hmid + (size_t)e * CAP * F_FF;
#pragma unroll
    for (int i = 0; i < 8; i++) {
        int m = m0 + ty + i * 16;
#pragma unroll
        for (int j = 0; j < 8; j++) {
            int n = n0 + tx + j * 16;
            float v = acc[i][j] + b1[e * F_FF + n];
            Hm[(size_t)m * F_FF + n] = fmaxf(v, 0.f);
        }
    }
}

// ---------------- GEMM2: y[token] = (hmid @ w2 + b2) * prob (fused combine)
// A: [CAP,1024] per expert   B: [1024,256] per expert   tile 128x128, BK=8
__global__ __launch_bounds__(256) void gemm2_kernel(const float* __restrict__ w2,
                                                    const float* __restrict__ b2,
                                                    float* __restrict__ y) {
    int e  = blockIdx.z;
    int m0 = blockIdx.y * 128;
    int n0 = blockIdx.x * 128;
    int cnt = g_count[e];
    if (m0 >= cnt) return;

    const float* A = g_hmid + (size_t)e * CAP * F_FF;
    const float* B = w2     + (size_t)e * F_FF * D_MODEL;

    __shared__ float As[8][128];
    __shared__ float Bs[8][128];

    int tid = threadIdx.x;
    int tx = tid & 15, ty = tid >> 4;
    int a_row = tid >> 1,  a_k = (tid & 1) * 4;
    int b_row = tid >> 5,  b_c = (tid & 31) * 4;

    float acc[8][8];
#pragma unroll
    for (int i = 0; i < 8; i++)
#pragma unroll
        for (int j = 0; j < 8; j++) acc[i][j] = 0.f;

    for (int k0 = 0; k0 < F_FF; k0 += 8) {
        float4 av = *(const float4*)(A + (size_t)(m0 + a_row) * F_FF + k0 + a_k);
        As[a_k + 0][a_row] = av.x; As[a_k + 1][a_row] = av.y;
        As[a_k + 2][a_row] = av.z; As[a_k + 3][a_row] = av.w;
        *(float4*)(&Bs[b_row][b_c]) =
            *(const float4*)(B + (size_t)(k0 + b_row) * D_MODEL + n0 + b_c);
        __syncthreads();
#pragma unroll
        for (int kk = 0; kk < 8; kk++) {
            float a[8], b[8];
#pragma unroll
            for (int i = 0; i < 8; i++) a[i] = As[kk][ty + i * 16];
#pragma unroll
            for (int j = 0; j < 8; j++) b[j] = Bs[kk][tx + j * 16];
#pragma unroll
            for (int i = 0; i < 8; i++)
#pragma unroll
                for (int j = 0; j < 8; j++) acc[i][j] += a[i] * b[j];
        }
        __syncthreads();
    }

#pragma unroll
    for (int i = 0; i < 8; i++) {
        int m = m0 + ty + i * 16;
        if (m < cnt) {
            int slot = e * CAP + m;
            int t = g_slot_token[slot];
            float p = g_slot_prob[slot];
            float* yr = y + (size_t)t * D_MODEL;
#pragma unroll
            for (int j = 0; j < 8; j++) {
                int n = n0 + tx + j * 16;
                yr[n] = (acc[i][j] + b2[e * D_MODEL + n]) * p;
            }
        }
    }
}

// ---------------- launch ----------------------------------------------------
extern "C" void kernel_launch(void* const* d_in, const int* in_sizes, int n_in,
                              void* d_out, int out_size) {
    const float* h      = (const float*)d_in[0];
    const float* gate_w = (const float*)d_in[1];
    const float* gate_b = (const float*)d_in[2];
    const float* w1     = (const float*)d_in[3];
    const float* b1     = (const float*)d_in[4];
    const float* w2     = (const float*)d_in[5];
    const float* b2     = (const float*)d_in[6];
    float* out = (float*)d_out;

    int n4 = out_size / 4;
    zero_kernel<<<(n4 + 255) / 256, 256>>>((float4*)out, n4);
    gate_kernel<<<T_TOKENS / 8, 256>>>(h, gate_w, gate_b);
    scan_kernel<<<1, 1024>>>();
    dispatch_kernel<<<E_EXPERTS * CAP / 4, 256>>>(h);
    gemm1_kernel<<<dim3(F_FF / 128, CAP / 128, E_EXPERTS), 256>>>(w1, b1);
    gemm2_kernel<<<dim3(D_MODEL / 128, CAP / 128, E_EXPERTS), 256>>>(w2, b2, out);
}

// round 10
// speedup vs baseline: 1.0122x; 1.0122x over previous
#include <cuda_runtime.h>
#include <math.h>
#include <stdint.h>

#define T_TOKENS 65536
#define D_MODEL  256
#define E_EXPERTS 8
#define F_FF     1024
#define CAP      10240

// ---------------- scratch (same footprint as passing R1) --------------------
__device__ __align__(128) float g_buf[(size_t)E_EXPERTS * CAP * D_MODEL];
__device__ __align__(128) float g_hmid[(size_t)E_EXPERTS * CAP * F_FF];
__device__ int   g_idx[T_TOKENS];
__device__ float g_prb[T_TOKENS];
__device__ int   g_slot_token[E_EXPERTS * CAP];
__device__ float g_slot_prob[E_EXPERTS * CAP];
__device__ int   g_count[E_EXPERTS];

// ---------------- packed f32x2 helpers ---------------------------------------
__device__ __forceinline__ void fma2(unsigned long long& c,
                                     unsigned long long a,
                                     unsigned long long b) {
    asm("fma.rn.f32x2 %0, %1, %2, %0;" : "+l"(c) : "l"(a), "l"(b));
}
__device__ __forceinline__ unsigned long long pack2(float v) {
    unsigned long long r;
    uint32_t u = __float_as_uint(v);
    asm("mov.b64 %0, {%1, %1};" : "=l"(r) : "r"(u));
    return r;
}
__device__ __forceinline__ void unpack2(unsigned long long v, float& lo, float& hi) {
    uint32_t a, b;
    asm("mov.b64 {%0, %1}, %2;" : "=r"(a), "=r"(b) : "l"(v));
    lo = __uint_as_float(a);
    hi = __uint_as_float(b);
}

// ---------------- prep kernels (verbatim from passing R1) --------------------
__global__ void zero_kernel(float4* __restrict__ out, int n4) {
    int i = blockIdx.x * blockDim.x + threadIdx.x;
    if (i < n4) out[i] = make_float4(0.f, 0.f, 0.f, 0.f);
}

__global__ void gate_kernel(const float* __restrict__ x,
                            const float* __restrict__ gw,
                            const float* __restrict__ gb) {
    __shared__ float s_gw[D_MODEL * E_EXPERTS];
    int tid = threadIdx.x;
    for (int i = tid; i < D_MODEL * E_EXPERTS; i += 256) s_gw[i] = gw[i];
    __syncthreads();
    int warp = tid >> 5, lane = tid & 31;
    int t = blockIdx.x * 8 + warp;
    const float* xr = x + (size_t)t * D_MODEL;
    float acc[E_EXPERTS];
#pragma unroll
    for (int e = 0; e < E_EXPERTS; e++) acc[e] = 0.f;
#pragma unroll
    for (int j = 0; j < 8; j++) {
        int d = j * 32 + lane;
        float xv = xr[d];
#pragma unroll
        for (int e = 0; e < E_EXPERTS; e++) acc[e] += xv * s_gw[d * E_EXPERTS + e];
    }
#pragma unroll
    for (int o = 16; o > 0; o >>= 1)
#pragma unroll
        for (int e = 0; e < E_EXPERTS; e++)
            acc[e] += __shfl_xor_sync(0xffffffffu, acc[e], o);
    if (lane == 0) {
        float lg[E_EXPERTS], m = -INFINITY; int am = 0;
#pragma unroll
        for (int e = 0; e < E_EXPERTS; e++) {
            lg[e] = acc[e] + gb[e];
            if (lg[e] > m) { m = lg[e]; am = e; }
        }
        float s = 0.f;
#pragma unroll
        for (int e = 0; e < E_EXPERTS; e++) s += expf(lg[e] - m);
        g_idx[t] = am;
        g_prb[t] = 1.0f / s;
    }
}

__global__ void scan_kernel() {
    __shared__ int s[1024][E_EXPERTS];
    int tid = threadIdx.x;
    int base = tid * (T_TOKENS / 1024);
    int cnt[E_EXPERTS];
#pragma unroll
    for (int e = 0; e < E_EXPERTS; e++) cnt[e] = 0;
    for (int i = 0; i < T_TOKENS / 1024; i++) cnt[g_idx[base + i]]++;
#pragma unroll
    for (int e = 0; e < E_EXPERTS; e++) s[tid][e] = cnt[e];
    __syncthreads();
    for (int off = 1; off < 1024; off <<= 1) {
        int v[E_EXPERTS];
        if (tid >= off)
#pragma unroll
            for (int e = 0; e < E_EXPERTS; e++) v[e] = s[tid - off][e];
        __syncthreads();
        if (tid >= off)
#pragma unroll
            for (int e = 0; e < E_EXPERTS; e++) s[tid][e] += v[e];
        __syncthreads();
    }
    int run[E_EXPERTS];
#pragma unroll
    for (int e = 0; e < E_EXPERTS; e++) run[e] = s[tid][e] - cnt[e];
    if (tid == 1023)
#pragma unroll
        for (int e = 0; e < E_EXPERTS; e++) g_count[e] = min(s[1023][e], CAP);
    for (int i = 0; i < T_TOKENS / 1024; i++) {
        int t = base + i;
        int e = g_idx[t];
        int pos = run[e]++;
        if (pos < CAP) {
            int slot = e * CAP + pos;
            g_slot_token[slot] = t;
            g_slot_prob[slot]  = g_prb[t];
        }
    }
}

__global__ void dispatch_kernel(const float* __restrict__ x) {
    int slot = blockIdx.x * 4 + (threadIdx.x >> 6);
    int e = slot / CAP, c = slot % CAP;
    if (c >= g_count[e]) return;
    int t = g_slot_token[slot];
    int i = threadIdx.x & 63;
    const float4* src = (const float4*)(x + (size_t)t * D_MODEL);
    float4* dst = (float4*)(g_buf + (size_t)slot * D_MODEL);
    dst[i] = src[i];
}

// ---------------- GEMM1: hmid = relu(buf @ w1 + b1), f32x2 FMA ---------------
// CTA 128m x 128n, BK=16. Thread (tx,ty): rows ty+i*16 (i<8), cols tx*8..tx*8+7.
__global__ __launch_bounds__(256) void gemm1_kernel(const float* __restrict__ w1,
                                                    const float* __restrict__ b1) {
    int e  = blockIdx.z;
    int m0 = blockIdx.y * 128;
    int n0 = blockIdx.x * 128;
    if (m0 >= g_count[e]) return;

    const float* A = g_buf + (size_t)e * CAP * D_MODEL;
    const float* B = w1    + (size_t)e * D_MODEL * F_FF;

    __shared__ float As[16][128];
    __shared__ float Bs[16][128];

    int tid = threadIdx.x;
    int tx = tid & 15, ty = tid >> 4;
    int a_row = tid >> 1,  a_k = (tid & 1) * 8;
    int b_row = tid >> 4,  b_c = (tid & 15) * 8;

    unsigned long long acc[8][4];
#pragma unroll
    for (int i = 0; i < 8; i++)
#pragma unroll
        for (int j = 0; j < 4; j++) acc[i][j] = 0ull;

    for (int k0 = 0; k0 < D_MODEL; k0 += 16) {
        float4 av0 = *(const float4*)(A + (size_t)(m0 + a_row) * D_MODEL + k0 + a_k);
        float4 av1 = *(const float4*)(A + (size_t)(m0 + a_row) * D_MODEL + k0 + a_k + 4);
        As[a_k + 0][a_row] = av0.x; As[a_k + 1][a_row] = av0.y;
        As[a_k + 2][a_row] = av0.z; As[a_k + 3][a_row] = av0.w;
        As[a_k + 4][a_row] = av1.x; As[a_k + 5][a_row] = av1.y;
        As[a_k + 6][a_row] = av1.z; As[a_k + 7][a_row] = av1.w;
        *(float4*)(&Bs[b_row][b_c]) =
            *(const float4*)(B + (size_t)(k0 + b_row) * F_FF + n0 + b_c);
        *(float4*)(&Bs[b_row][b_c + 4]) =
            *(const float4*)(B + (size_t)(k0 + b_row) * F_FF + n0 + b_c + 4);
        __syncthreads();
#pragma unroll
        for (int kk = 0; kk < 16; kk++) {
            const unsigned long long* pb =
                (const unsigned long long*)(&Bs[kk][tx * 8]);
            unsigned long long bp0 = pb[0], bp1 = pb[1], bp2 = pb[2], bp3 = pb[3];
#pragma unroll
            for (int i = 0; i < 8; i++) {
                unsigned long long ap = pack2(As[kk][ty + i * 16]);
                fma2(acc[i][0], ap, bp0);
                fma2(acc[i][1], ap, bp1);
                fma2(acc[i][2], ap, bp2);
                fma2(acc[i][3], ap, bp3);
            }
        }
        __syncthreads();
    }

    float* Hm = g_hmid + (size_t)e * CAP * F_FF;
    int n = n0 + tx * 8;
    float4 bv0 = *(const float4*)(b1 + e * F_FF + n);
    float4 bv1 = *(const float4*)(b1 + e * F_FF + n + 4);
#pragma unroll
    for (int i = 0; i < 8; i++) {
        int m = m0 + ty + i * 16;
        float o[8];
#pragma unroll
        for (int j = 0; j < 4; j++) unpack2(acc[i][j], o[j * 2], o[j * 2 + 1]);
        float4 r0, r1;
        r0.x = fmaxf(o[0] + bv0.x, 0.f); r0.y = fmaxf(o[1] + bv0.y, 0.f);
        r0.z = fmaxf(o[2] + bv0.z, 0.f); r0.w = fmaxf(o[3] + bv0.w, 0.f);
        r1.x = fmaxf(o[4] + bv1.x, 0.f); r1.y = fmaxf(o[5] + bv1.y, 0.f);
        r1.z = fmaxf(o[6] + bv1.z, 0.f); r1.w = fmaxf(o[7] + bv1.w, 0.f);
        *(float4*)(Hm + (size_t)m * F_FF + n)     = r0;
        *(float4*)(Hm + (size_t)m * F_FF + n + 4) = r1;
    }
}

// ---------------- GEMM2: y[token] = (hmid @ w2 + b2) * prob ------------------
__global__ __launch_bounds__(256) void gemm2_kernel(const float* __restrict__ w2,
                                                    const float* __restrict__ b2,
                                                    float* __restrict__ y) {
    int e  = blockIdx.z;
    int m0 = blockIdx.y * 128;
    int n0 = blockIdx.x * 128;
    int cnt = g_count[e];
    if (m0 >= cnt) return;

    const float* A = g_hmid + (size_t)e * CAP * F_FF;
    const float* B = w2     + (size_t)e * F_FF * D_MODEL;

    __shared__ float As[16][128];
    __shared__ float Bs[16][128];

    int tid = threadIdx.x;
    int tx = tid & 15, ty = tid >> 4;
    int a_row = tid >> 1,  a_k = (tid & 1) * 8;
    int b_row = tid >> 4,  b_c = (tid & 15) * 8;

    unsigned long long acc[8][4];
#pragma unroll
    for (int i = 0; i < 8; i++)
#pragma unroll
        for (int j = 0; j < 4; j++) acc[i][j] = 0ull;

    for (int k0 = 0; k0 < F_FF; k0 += 16) {
        float4 av0 = *(const float4*)(A + (size_t)(m0 + a_row) * F_FF + k0 + a_k);
        float4 av1 = *(const float4*)(A + (size_t)(m0 + a_row) * F_FF + k0 + a_k + 4);
        As[a_k + 0][a_row] = av0.x; As[a_k + 1][a_row] = av0.y;
        As[a_k + 2][a_row] = av0.z; As[a_k + 3][a_row] = av0.w;
        As[a_k + 4][a_row] = av1.x; As[a_k + 5][a_row] = av1.y;
        As[a_k + 6][a_row] = av1.z; As[a_k + 7][a_row] = av1.w;
        *(float4*)(&Bs[b_row][b_c]) =
            *(const float4*)(B + (size_t)(k0 + b_row) * D_MODEL + n0 + b_c);
        *(float4*)(&Bs[b_row][b_c + 4]) =
            *(const float4*)(B + (size_t)(k0 + b_row) * D_MODEL + n0 + b_c + 4);
        __syncthreads();
#pragma unroll
        for (int kk = 0; kk < 16; kk++) {
            const unsigned long long* pb =
                (const unsigned long long*)(&Bs[kk][tx * 8]);
            unsigned long long bp0 = pb[0], bp1 = pb[1], bp2 = pb[2], bp3 = pb[3];
#pragma unroll
            for (int i = 0; i < 8; i++) {
                unsigned long long ap = pack2(As[kk][ty + i * 16]);
                fma2(acc[i][0], ap, bp0);
                fma2(acc[i][1], ap, bp1);
                fma2(acc[i][2], ap, bp2);
                fma2(acc[i][3], ap, bp3);
            }
        }
        __syncthreads();
    }

    int n = n0 + tx * 8;
    float4 bv0 = *(const float4*)(b2 + e * D_MODEL + n);
    float4 bv1 = *(const float4*)(b2 + e * D_MODEL + n + 4);
#pragma unroll
    for (int i = 0; i < 8; i++) {
        int m = m0 + ty + i * 16;
        if (m < cnt) {
            int slot = e * CAP + m;
            int t = g_slot_token[slot];
            float p = g_slot_prob[slot];
            float o[8];
#pragma unroll
            for (int j = 0; j < 4; j++) unpack2(acc[i][j], o[j * 2], o[j * 2 + 1]);
            float4 r0, r1;
            r0.x = (o[0] + bv0.x) * p; r0.y = (o[1] + bv0.y) * p;
            r0.z = (o[2] + bv0.z) * p; r0.w = (o[3] + bv0.w) * p;
            r1.x = (o[4] + bv1.x) * p; r1.y = (o[5] + bv1.y) * p;
            r1.z = (o[6] + bv1.z) * p; r1.w = (o[7] + bv1.w) * p;
            float* yr = y + (size_t)t * D_MODEL + n;
            *(float4*)(yr)     = r0;
            *(float4*)(yr + 4) = r1;
        }
    }
}

// ---------------- launch ------------------------------------------------------
extern "C" void kernel_launch(void* const* d_in, const int* in_sizes, int n_in,
                              void* d_out, int out_size) {
    const float* h      = (const float*)d_in[0];
    const float* gate_w = (const float*)d_in[1];
    const float* gate_b = (const float*)d_in[2];
    const float* w1     = (const float*)d_in[3];
    const float* b1     = (const float*)d_in[4];
    const float* w2     = (const float*)d_in[5];
    const float* b2     = (const float*)d_in[6];
    float* out = (float*)d_out;

    int n4 = out_size / 4;
    zero_kernel<<<(n4 + 255) / 256, 256>>>((float4*)out, n4);
    gate_kernel<<<T_TOKENS / 8, 256>>>(h, gate_w, gate_b);
    scan_kernel<<<1, 1024>>>();
    dispatch_kernel<<<E_EXPERTS * CAP / 4, 256>>>(h);
    gemm1_kernel<<<dim3(F_FF / 128, CAP / 128, E_EXPERTS), 256>>>(w1, b1);
    gemm2_kernel<<<dim3(D_MODEL / 128, CAP / 128, E_EXPERTS), 256>>>(w2, b2, out);
}